// round 13
// baseline (speedup 1.0000x reference)
#include <cuda_runtime.h>
#include <cstdint>

// ---------------- problem constants ----------------
#define NB       16
#define N_F      524288
#define N_P      65536
#define EH       2097152
#define E_TOTAL  4194304
#define L0       4096
#define L1V      4095
#define L2V      4094
#define KDIM     409400
#define O1       500
#define NCLS     107

// ---------------- packed fp32x2 helpers ----------------
__device__ __forceinline__ double pk2(float lo, float hi) {
    double d; asm("mov.b64 %0, {%1, %2};" : "=d"(d) : "f"(lo), "f"(hi)); return d;
}
__device__ __forceinline__ void upk2(double d, float& lo, float& hi) {
    asm("mov.b64 {%0, %1}, %2;" : "=f"(lo), "=f"(hi) : "d"(d));
}
__device__ __forceinline__ double ffma2(double a, double b, double c) {
    double d; asm("fma.rn.f32x2 %0, %1, %2, %3;" : "=d"(d) : "d"(a), "d"(b), "d"(c)); return d;
}
__device__ __forceinline__ double fadd2(double a, double b) {
    double d; asm("add.rn.f32x2 %0, %1, %2;" : "=d"(d) : "d"(a), "d"(b)); return d;
}

// ---------------- scratch ----------------
__device__ float4 g_xf4[N_F];
__device__ float g_agg[N_P * 4];
__device__ float g_out1[NB * 100 * L1V];
__device__ float g_out2[NB * 100 * L2V];
__device__ float g_y1[O1 * NB];

// ---------------- feat (+ fused zero-init) ----------------
#define FEAT_SMEM ((64 * 65 + 192 * 65) * 4)
__global__ __launch_bounds__(256)
void feat_kernel(const float* __restrict__ xsrc,
                 const float* __restrict__ Wfd,
                 const float* __restrict__ bfd) {
    int t0 = blockIdx.x * 256 + threadIdx.x;
#pragma unroll
    for (int z = t0; z < N_P * 4; z += 32768) g_agg[z] = 0.0f;
    if (t0 < O1 * NB) g_y1[t0] = 0.0f;

    extern __shared__ float sm[];
    float* xs = sm;             // [64][65]
    float* ws = sm + 64 * 65;   // [192][65]
    int t = threadIdx.x;
    int i0 = blockIdx.x << 6;

    for (int idx = t; idx < 4096; idx += 256) {
        int i = idx >> 6, k = idx & 63;
        xs[i * 65 + k] = xsrc[(i0 + i) * 64 + k];
    }
    for (int idx = t; idx < 12288; idx += 256) {
        int j = idx >> 6, k = idx & 63;
        ws[j * 65 + k] = Wfd[idx];
    }
    __syncthreads();

    int tx = t & 15, ty = t >> 4;
    float acc[4][12];
#pragma unroll
    for (int ii = 0; ii < 4; ii++)
#pragma unroll
        for (int jj = 0; jj < 12; jj++) acc[ii][jj] = 0.0f;

    for (int k = 0; k < 64; k++) {
        float xv[4], wv[12];
#pragma unroll
        for (int ii = 0; ii < 4; ii++) xv[ii] = xs[(ty * 4 + ii) * 65 + k];
#pragma unroll
        for (int jj = 0; jj < 12; jj++) wv[jj] = ws[(tx * 12 + jj) * 65 + k];
#pragma unroll
        for (int ii = 0; ii < 4; ii++)
#pragma unroll
            for (int jj = 0; jj < 12; jj++)
                acc[ii][jj] = fmaf(xv[ii], wv[jj], acc[ii][jj]);
    }

    int j0 = tx * 12;
#pragma unroll
    for (int ii = 0; ii < 4; ii++) {
        int i = i0 + ty * 4 + ii;
#pragma unroll
        for (int rr = 0; rr < 4; rr++) {
            int r = i * 64 + tx * 4 + rr;
            g_xf4[r] = make_float4(
                acc[ii][rr * 3 + 0] + __ldg(bfd + j0 + rr * 3 + 0),
                acc[ii][rr * 3 + 1] + __ldg(bfd + j0 + rr * 3 + 1),
                acc[ii][rr * 3 + 2] + __ldg(bfd + j0 + rr * 3 + 2),
                0.0f);
        }
    }
}

// ---------------- edge aggregation ----------------
__global__ void edge_kernel(const int* __restrict__ ei) {
    int e2 = blockIdx.x * 256 + threadIdx.x;
    int4 s4 = *reinterpret_cast<const int4*>(ei + 4 * e2);
    int4 d4 = *reinterpret_cast<const int4*>(ei + E_TOTAL + 4 * e2);
    float4 v0 = g_xf4[s4.x];
    float4 v1 = g_xf4[s4.z];
    float* a0 = g_agg + 4 * d4.x;
    float* a1 = g_agg + 4 * d4.z;
    asm volatile("red.global.add.v4.f32 [%0], {%1, %2, %3, %4};"
                 :: "l"(a0), "f"(v0.x), "f"(v0.y), "f"(v0.z), "f"(1.0f) : "memory");
    asm volatile("red.global.add.v4.f32 [%0], {%1, %2, %3, %4};"
                 :: "l"(a1), "f"(v1.x), "f"(v1.y), "f"(v1.z), "f"(1.0f) : "memory");
}

// ================= conv v2 common layout =========================================
// block 200 thr = 25 og x 8 ht. o-split: 50 o per block (grid.z=2), 2 o per thread.
// h-tile 32: 4 h per thread. xs2 = interleaved x-pair array:
//   pair p stored at double-slot ((p&3)*8 + (p>>2)), row = 64 words.
//   thread ht reads pairs p = q*8.. wait: reads slots q*8+ht -> conflict-free LDS.64.

__device__ __forceinline__ void conv_core(const float* ws, const float* xs2f,
                                          float* __restrict__ out, int b, int h0,
                                          int oz, int t, int Lout) {
    int og = t >> 3, ht = t & 7;
    int o0 = og << 1;
    double acc2[2][4];
#pragma unroll
    for (int oo = 0; oo < 2; oo++)
#pragma unroll
        for (int q = 0; q < 4; q++) acc2[oo][q] = 0.0;

    for (int i = 0; i < 100; i++) {
        const double* xrow = reinterpret_cast<const double*>(xs2f + i * 64);
        double xp[4];
#pragma unroll
        for (int q = 0; q < 4; q++) xp[q] = xrow[q * 8 + ht];
#pragma unroll
        for (int oo = 0; oo < 2; oo++) {
            double wp = *reinterpret_cast<const double*>(&ws[(o0 + oo) * 202 + i * 2]);
#pragma unroll
            for (int q = 0; q < 4; q++)
                acc2[oo][q] = ffma2(wp, xp[q], acc2[oo][q]);
        }
    }

#pragma unroll
    for (int oo = 0; oo < 2; oo++) {
        int orow = oz + o0 + oo;
        int h = h0 + (ht << 2);
        float* dst = out + (size_t)b * 100 * Lout + (size_t)orow * Lout + h;
        // SCALAR stores: Lout is odd/even-non-mult-4, row stride breaks 16B alignment
#pragma unroll
        for (int q = 0; q < 4; q++) {
            float lo, hi; upk2(acc2[oo][q], lo, hi);
            if (h + q < Lout) dst[q] = fmaxf(lo + hi, 0.0f);
        }
    }
}

// store value v as halves of pairs p=jx (.lo) and p=jx-1 (.hi)
__device__ __forceinline__ void xpair_store(float* xs2f, int i, int jx, float v) {
    float* row = xs2f + i * 64;
    if (jx < 32) { int p = jx;     row[(((p & 3) << 3) | (p >> 2)) * 2]     = v; }
    if (jx > 0)  { int p = jx - 1; row[(((p & 3) << 3) | (p >> 2)) * 2 + 1] = v; }
}

// ---------------- conv1 (node-update fused) ----------------
#define C1_SMEM ((50 * 202 + 100 * 64 + 704) * 4)
__global__ __launch_bounds__(200, 3)
void conv1_kernel(const float* __restrict__ xdst,
                  const float* __restrict__ Wl1,
                  const float* __restrict__ bl1,
                  const float* __restrict__ Wr1,
                  const float* __restrict__ Wc1,
                  float* __restrict__ out) {
    extern __shared__ float sm[];
    float* ws   = sm;                 // [50][202]
    float* xs2f = sm + 50 * 202;      // [100][64]
    float* swl  = xs2f + 100 * 64;    // 300
    float* swr  = swl + 300;          // 300
    float* sb   = swr + 300;          // 100
    int b  = blockIdx.x;
    int h0 = blockIdx.y << 5;
    int oz = blockIdx.z * 50;
    int t  = threadIdx.x;

    for (int idx = t; idx < 10000; idx += 200) {
        int o = idx / 200;
        ws[o * 202 + (idx - o * 200)] = Wc1[(oz + o) * 200 + (idx - o * 200)];
    }
    for (int idx = t; idx < 300; idx += 200) { swl[idx] = Wl1[idx]; swr[idx] = Wr1[idx]; }
    if (t < 100) sb[t] = bl1[t];
    __syncthreads();

    int nj = L0 - h0; if (nj > 33) nj = 33;
    for (int idx = t; idx < 3300; idx += 200) {
        int i = idx / 33, jx = idx - i * 33;
        float v = 0.0f;
        if (jx < nj) {
            int q  = i * 4096 + h0 + jx;
            int nl = q / 100;
            int c  = q - nl * 100;
            int n  = b * 4096 + nl;
            float4 a = *reinterpret_cast<const float4*>(&g_agg[n * 4]);
            float inv = __fdividef(1.0f, fmaxf(a.w, 1.0f));
            const float* xd = xdst + 3 * n;
            v = sb[c];
            v = fmaf(a.x * inv, swl[c * 3 + 0], v);
            v = fmaf(a.y * inv, swl[c * 3 + 1], v);
            v = fmaf(a.z * inv, swl[c * 3 + 2], v);
            v = fmaf(xd[0], swr[c * 3 + 0], v);
            v = fmaf(xd[1], swr[c * 3 + 1], v);
            v = fmaf(xd[2], swr[c * 3 + 2], v);
            v = fmaxf(v, 0.0f);
        }
        xpair_store(xs2f, i, jx, v);
    }
    __syncthreads();

    conv_core(ws, xs2f, out, b, h0, oz, t, L1V);
}

// ---------------- conv2 ----------------
#define C2_SMEM ((50 * 202 + 100 * 64) * 4)
__global__ __launch_bounds__(200, 3)
void conv2_kernel(const float* __restrict__ in, const float* __restrict__ W,
                  float* __restrict__ out, int Lin, int Lout) {
    extern __shared__ float sm[];
    float* ws   = sm;              // [50][202]
    float* xs2f = sm + 50 * 202;   // [100][64]
    int b  = blockIdx.x;
    int h0 = blockIdx.y << 5;
    int oz = blockIdx.z * 50;
    int t  = threadIdx.x;

    for (int idx = t; idx < 10000; idx += 200) {
        int o = idx / 200;
        ws[o * 202 + (idx - o * 200)] = W[(oz + o) * 200 + (idx - o * 200)];
    }
    int nj = Lin - h0; if (nj > 33) nj = 33;
    const float* inb = in + (size_t)b * 100 * Lin + h0;
    for (int idx = t; idx < 3300; idx += 200) {
        int i = idx / 33, jx = idx - i * 33;
        float v = (jx < nj) ? inb[(size_t)i * Lin + jx] : 0.0f;
        xpair_store(xs2f, i, jx, v);
    }
    __syncthreads();

    conv_core(ws, xs2f, out, b, h0, oz, t, Lout);
}

// ---------------- dense1 v4 (best measured; untouched) ----------------
#define D1_SMEM (1024 * 20 * 4)
__global__ __launch_bounds__(256, 2)
void dense1_kernel(const float* __restrict__ x2, const float* __restrict__ W) {
    extern __shared__ float xs[];   // [1024][20]
    int t = threadIdx.x;
    int k0 = blockIdx.x << 10;
    int KN = KDIM - k0; if (KN > 1024) KN = 1024;

    for (int idx = t; idx < 4096; idx += 256) {
        int b  = idx & 15;
        int kk = (idx >> 4) << 2;
        float4 v = make_float4(0.f, 0.f, 0.f, 0.f);
        if (kk < KN)
            v = *reinterpret_cast<const float4*>(x2 + (size_t)b * KDIM + k0 + kk);
        xs[(kk + 0) * 20 + b] = v.x;
        xs[(kk + 1) * 20 + b] = v.y;
        xs[(kk + 2) * 20 + b] = v.z;
        xs[(kk + 3) * 20 + b] = v.w;
    }
    __syncthreads();

    int wid = t >> 5, lane = t & 31;
    int o0 = (blockIdx.y << 5) + (wid << 2);
    if (o0 >= O1) return;

    double acc2[4][8];
#pragma unroll
    for (int o = 0; o < 4; o++)
#pragma unroll
        for (int bp = 0; bp < 8; bp++) acc2[o][bp] = 0.0;

    const float* wbase = W + (size_t)o0 * KDIM + k0;

    float wbuf[4][4];
#pragma unroll
    for (int p = 0; p < 4; p++) {
        int k = lane + (p << 5);
#pragma unroll
        for (int o = 0; o < 4; o++)
            wbuf[p][o] = (k < KN) ? __ldg(wbase + (size_t)o * KDIM + k) : 0.0f;
    }

#pragma unroll 4
    for (int it = 0; it < 32; it++) {
        int slot = it & 3;
        int k = lane + (it << 5);

        double wd[4];
#pragma unroll
        for (int o = 0; o < 4; o++) wd[o] = pk2(wbuf[slot][o], wbuf[slot][o]);

        int kn = k + 128;
#pragma unroll
        for (int o = 0; o < 4; o++)
            wbuf[slot][o] = (kn < KN) ? __ldg(wbase + (size_t)o * KDIM + kn) : 0.0f;

        const double2* xrow = reinterpret_cast<const double2*>(&xs[k * 20]);
        double2 x01 = xrow[0], x23 = xrow[1], x45 = xrow[2], x67 = xrow[3];
        double xp[8] = {x01.x, x01.y, x23.x, x23.y, x45.x, x45.y, x67.x, x67.y};

#pragma unroll
        for (int o = 0; o < 4; o++)
#pragma unroll
            for (int bp = 0; bp < 8; bp++)
                acc2[o][bp] = ffma2(wd[o], xp[bp], acc2[o][bp]);
    }

    double s2[32];
#pragma unroll
    for (int a = 0; a < 32; a++) s2[a] = acc2[a >> 3][a & 7];
    int n = 32;
#pragma unroll
    for (int d = 16; d >= 1; d >>= 1) {
        n >>= 1;
        bool hiSel = (lane & d) != 0;
#pragma unroll
        for (int i = 0; i < 16; i++) {
            if (i >= n) break;
            double send = hiSel ? s2[i] : s2[i + n];
            double recv = __shfl_xor_sync(0xffffffffu, send, d);
            double keep = hiSel ? s2[i + n] : s2[i];
            s2[i] = fadd2(keep, recv);
        }
    }
    float lo, hi; upk2(s2[0], lo, hi);
    float* addr = &g_y1[(o0 + (lane >> 3)) * 16 + 2 * (lane & 7)];
    asm volatile("red.global.add.v2.f32 [%0], {%1, %2};"
                 :: "l"(addr), "f"(lo), "f"(hi) : "memory");
}

// ---------------- dense2 + softmax ----------------
__global__ void dense2_kernel(const float* __restrict__ Wd2, float* __restrict__ out) {
    __shared__ float ys[O1];
    __shared__ float red[128];
    int b = blockIdx.x, t = threadIdx.x;
    for (int o = t; o < O1; o += 128) ys[o] = fmaxf(g_y1[o * 16 + b], 0.0f);
    __syncthreads();

    float logit = -1e30f;
    if (t < NCLS) {
        float s = 0.0f;
        const float* wr = Wd2 + t * O1;
        for (int o = 0; o < O1; o++) s = fmaf(ys[o], __ldg(wr + o), s);
        logit = s;
    }
    red[t] = logit;
    __syncthreads();
    for (int s = 64; s > 0; s >>= 1) {
        if (t < s) red[t] = fmaxf(red[t], red[t + s]);
        __syncthreads();
    }
    float mx = red[0];
    __syncthreads();
    float e = (t < NCLS) ? expf(logit - mx) : 0.0f;
    red[t] = e;
    __syncthreads();
    for (int s = 64; s > 0; s >>= 1) {
        if (t < s) red[t] += red[t + s];
        __syncthreads();
    }
    float sum = red[0];
    if (t < NCLS) out[b * NCLS + t] = e / sum;
}

// ---------------- launch ----------------
extern "C" void kernel_launch(void* const* d_in, const int* in_sizes, int n_in,
                              void* d_out, int out_size) {
    const float* x_src = (const float*)d_in[0];
    const float* x_dst = (const float*)d_in[1];
    const int*   ei    = (const int*)  d_in[2];
    const float* Wfd   = (const float*)d_in[3];
    const float* bfd   = (const float*)d_in[4];
    const float* Wl1   = (const float*)d_in[5];
    const float* bl1   = (const float*)d_in[6];
    const float* Wr1   = (const float*)d_in[7];
    const float* Wc1   = (const float*)d_in[11];
    const float* Wc2   = (const float*)d_in[12];
    const float* Wd1   = (const float*)d_in[13];
    const float* Wd2   = (const float*)d_in[14];
    float* out = (float*)d_out;

    float *p_o1, *p_o2;
    cudaGetSymbolAddress((void**)&p_o1, g_out1);
    cudaGetSymbolAddress((void**)&p_o2, g_out2);

    cudaFuncSetAttribute(feat_kernel,   cudaFuncAttributeMaxDynamicSharedMemorySize, FEAT_SMEM);
    cudaFuncSetAttribute(conv1_kernel,  cudaFuncAttributeMaxDynamicSharedMemorySize, C1_SMEM);
    cudaFuncSetAttribute(conv1_kernel,  cudaFuncAttributePreferredSharedMemoryCarveout, 100);
    cudaFuncSetAttribute(conv2_kernel,  cudaFuncAttributeMaxDynamicSharedMemorySize, C2_SMEM);
    cudaFuncSetAttribute(conv2_kernel,  cudaFuncAttributePreferredSharedMemoryCarveout, 100);
    cudaFuncSetAttribute(dense1_kernel, cudaFuncAttributeMaxDynamicSharedMemorySize, D1_SMEM);
    cudaFuncSetAttribute(dense1_kernel, cudaFuncAttributePreferredSharedMemoryCarveout, 100);

    feat_kernel<<<128, 256, FEAT_SMEM>>>(x_src, Wfd, bfd);                   // #1
    edge_kernel<<<4096, 256>>>(ei);                                          // #2
    conv1_kernel<<<dim3(16, 128, 2), 200, C1_SMEM>>>(x_dst, Wl1, bl1, Wr1, Wc1, p_o1); // #3
    conv2_kernel<<<dim3(16, 128, 2), 200, C2_SMEM>>>(p_o1, Wc2, p_o2, L1V, L2V);       // #4
    dense1_kernel<<<dim3(400, 16), 256, D1_SMEM>>>(p_o2, Wd1);               // #5
    dense2_kernel<<<NB, 128>>>(Wd2, out);                                    // #6
}

// round 14
// speedup vs baseline: 1.0505x; 1.0505x over previous
#include <cuda_runtime.h>
#include <cstdint>

// ---------------- problem constants ----------------
#define NB       16
#define N_F      524288
#define N_P      65536
#define EH       2097152
#define E_TOTAL  4194304
#define XP_N     6553600
#define L0       4096
#define L1V      4095
#define L2V      4094
#define KDIM     409400
#define O1       500
#define NCLS     107

// ---------------- packed fp32x2 helpers ----------------
__device__ __forceinline__ double pk2(float lo, float hi) {
    double d; asm("mov.b64 %0, {%1, %2};" : "=d"(d) : "f"(lo), "f"(hi)); return d;
}
__device__ __forceinline__ void upk2(double d, float& lo, float& hi) {
    asm("mov.b64 {%0, %1}, %2;" : "=f"(lo), "=f"(hi) : "d"(d));
}
__device__ __forceinline__ double ffma2(double a, double b, double c) {
    double d; asm("fma.rn.f32x2 %0, %1, %2, %3;" : "=d"(d) : "d"(a), "d"(b), "d"(c)); return d;
}
__device__ __forceinline__ double fadd2(double a, double b) {
    double d; asm("add.rn.f32x2 %0, %1, %2;" : "=d"(d) : "d"(a), "d"(b)); return d;
}

// ---------------- scratch ----------------
__device__ float4 g_xf4[N_F];
__device__ float g_agg[N_P * 4];
__device__ float g_xp[XP_N];
__device__ float g_out1[NB * 100 * L1V];
__device__ float g_out2[NB * 100 * L2V];
__device__ float g_y1[O1 * NB];

// ---------------- zero init ----------------
__global__ void zero_kernel() {
    int i = blockIdx.x * 256 + threadIdx.x;
    if (i < N_P * 4) g_agg[i] = 0.0f;
    if (i < O1 * NB) g_y1[i] = 0.0f;
}

// ---------------- feat: 8192x64 @ 64x192 -> g_xf4 ----------------
#define FEAT_SMEM ((64 * 65 + 192 * 65) * 4)
__global__ __launch_bounds__(256)
void feat_kernel(const float* __restrict__ xsrc,
                 const float* __restrict__ Wfd,
                 const float* __restrict__ bfd) {
    extern __shared__ float sm[];
    float* xs = sm;             // [64][65]
    float* ws = sm + 64 * 65;   // [192][65]
    int t = threadIdx.x;
    int i0 = blockIdx.x << 6;

    for (int idx = t; idx < 4096; idx += 256) {
        int i = idx >> 6, k = idx & 63;
        xs[i * 65 + k] = xsrc[(i0 + i) * 64 + k];
    }
    for (int idx = t; idx < 12288; idx += 256) {
        int j = idx >> 6, k = idx & 63;
        ws[j * 65 + k] = Wfd[idx];
    }
    __syncthreads();

    int tx = t & 15, ty = t >> 4;
    float acc[4][12];
#pragma unroll
    for (int ii = 0; ii < 4; ii++)
#pragma unroll
        for (int jj = 0; jj < 12; jj++) acc[ii][jj] = 0.0f;

    for (int k = 0; k < 64; k++) {
        float xv[4], wv[12];
#pragma unroll
        for (int ii = 0; ii < 4; ii++) xv[ii] = xs[(ty * 4 + ii) * 65 + k];
#pragma unroll
        for (int jj = 0; jj < 12; jj++) wv[jj] = ws[(tx * 12 + jj) * 65 + k];
#pragma unroll
        for (int ii = 0; ii < 4; ii++)
#pragma unroll
            for (int jj = 0; jj < 12; jj++)
                acc[ii][jj] = fmaf(xv[ii], wv[jj], acc[ii][jj]);
    }

    int j0 = tx * 12;
#pragma unroll
    for (int ii = 0; ii < 4; ii++) {
        int i = i0 + ty * 4 + ii;
#pragma unroll
        for (int rr = 0; rr < 4; rr++) {
            int r = i * 64 + tx * 4 + rr;
            g_xf4[r] = make_float4(
                acc[ii][rr * 3 + 0] + __ldg(bfd + j0 + rr * 3 + 0),
                acc[ii][rr * 3 + 1] + __ldg(bfd + j0 + rr * 3 + 1),
                acc[ii][rr * 3 + 2] + __ldg(bfd + j0 + rr * 3 + 2),
                0.0f);
        }
    }
}

// ---------------- edge aggregation ----------------
__global__ void edge_kernel(const int* __restrict__ ei) {
    int e2 = blockIdx.x * 256 + threadIdx.x;
    int4 s4 = *reinterpret_cast<const int4*>(ei + 4 * e2);
    int4 d4 = *reinterpret_cast<const int4*>(ei + E_TOTAL + 4 * e2);
    float4 v0 = g_xf4[s4.x];
    float4 v1 = g_xf4[s4.z];
    float* a0 = g_agg + 4 * d4.x;
    float* a1 = g_agg + 4 * d4.z;
    asm volatile("red.global.add.v4.f32 [%0], {%1, %2, %3, %4};"
                 :: "l"(a0), "f"(v0.x), "f"(v0.y), "f"(v0.z), "f"(1.0f) : "memory");
    asm volatile("red.global.add.v4.f32 [%0], {%1, %2, %3, %4};"
                 :: "l"(a1), "f"(v1.x), "f"(v1.y), "f"(v1.z), "f"(1.0f) : "memory");
}

// ---------------- node update ----------------
__global__ __launch_bounds__(256)
void node_kernel(const float* __restrict__ xdst,
                 const float* __restrict__ Wl1,
                 const float* __restrict__ bl1,
                 const float* __restrict__ Wr1) {
    __shared__ float swl[300], swr[300], sb[100];
    int t = threadIdx.x;
    for (int idx = t; idx < 300; idx += 256) { swl[idx] = Wl1[idx]; swr[idx] = Wr1[idx]; }
    if (t < 100) sb[t] = bl1[t];
    __syncthreads();

    int gid = blockIdx.x * 256 + t;
    int n = gid / 25;
    int c0 = (gid - n * 25) * 4;
    float4 a = *reinterpret_cast<const float4*>(&g_agg[n * 4]);
    float inv = __fdividef(1.0f, fmaxf(a.w, 1.0f));
    float m0 = a.x * inv, m1 = a.y * inv, m2 = a.z * inv;
    const float* xd = xdst + 3 * n;
    float d0 = xd[0], d1 = xd[1], d2 = xd[2];
    float r[4];
#pragma unroll
    for (int cc = 0; cc < 4; cc++) {
        int c = c0 + cc;
        float v = sb[c];
        v = fmaf(m0, swl[c * 3 + 0], v);
        v = fmaf(m1, swl[c * 3 + 1], v);
        v = fmaf(m2, swl[c * 3 + 2], v);
        v = fmaf(d0, swr[c * 3 + 0], v);
        v = fmaf(d1, swr[c * 3 + 1], v);
        v = fmaf(d2, swr[c * 3 + 2], v);
        r[cc] = fmaxf(v, 0.0f);
    }
    *reinterpret_cast<float4*>(&g_xp[n * 100 + c0]) =
        make_float4(r[0], r[1], r[2], r[3]);
}

// ---------------- conv (R11-measured version: 123us) ----------------
#define CONV_SMEM ((100 * 202 + 100 * 68) * 4)
__global__ __launch_bounds__(200, 2)
void conv_kernel(const float* __restrict__ in, const float* __restrict__ W,
                 float* __restrict__ out, int Lin, int Lout) {
    extern __shared__ float sm[];
    float* ws = sm;               // [o][202]
    float* xs = sm + 100 * 202;   // [i][68]
    int b  = blockIdx.x;
    int h0 = blockIdx.y << 6;
    int t  = threadIdx.x;

    for (int idx = t; idx < 20000; idx += 200) {
        int o = idx / 200;
        ws[o * 202 + (idx - o * 200)] = W[idx];
    }
    int nj = Lin - h0; if (nj > 65) nj = 65;
    const float* inb = in + b * 100 * Lin + h0;
    for (int idx = t; idx < 6800; idx += 200) {
        int i = idx / 68;
        int j = idx - i * 68;
        xs[idx] = (j < nj) ? inb[i * Lin + j] : 0.0f;
    }
    __syncthreads();

    int og = t >> 3, ht = t & 7;
    int o0 = og << 2, hh = ht << 3;
    double acc2[4][8];
#pragma unroll
    for (int oo = 0; oo < 4; oo++)
#pragma unroll
        for (int j = 0; j < 8; j++) acc2[oo][j] = 0.0;

    for (int i = 0; i < 100; i++) {
        const float* xr = xs + i * 68 + hh;
        float4 xA = *reinterpret_cast<const float4*>(xr);
        float4 xB = *reinterpret_cast<const float4*>(xr + 4);
        float x8 = xr[8];
        double xp[8];
        xp[0] = pk2(xA.x, xA.y); xp[1] = pk2(xA.y, xA.z);
        xp[2] = pk2(xA.z, xA.w); xp[3] = pk2(xA.w, xB.x);
        xp[4] = pk2(xB.x, xB.y); xp[5] = pk2(xB.y, xB.z);
        xp[6] = pk2(xB.z, xB.w); xp[7] = pk2(xB.w, x8);
#pragma unroll
        for (int oo = 0; oo < 4; oo++) {
            double wp = *reinterpret_cast<const double*>(&ws[(o0 + oo) * 202 + i * 2]);
#pragma unroll
            for (int j = 0; j < 8; j++)
                acc2[oo][j] = ffma2(wp, xp[j], acc2[oo][j]);
        }
    }

    float* outb = out + b * 100 * Lout;
#pragma unroll
    for (int oo = 0; oo < 4; oo++)
#pragma unroll
        for (int j = 0; j < 8; j++) {
            int h = h0 + hh + j;
            if (h < Lout) {
                float lo, hi; upk2(acc2[oo][j], lo, hi);
                outb[(o0 + oo) * Lout + h] = fmaxf(lo + hi, 0.0f);
            }
        }
}

// ---------------- dense1 v8: v4 + half-iteration x-LDS software pipeline ---------
#define D1_SMEM (1024 * 20 * 4)
__global__ __launch_bounds__(256, 2)
void dense1_kernel(const float* __restrict__ x2, const float* __restrict__ W) {
    extern __shared__ float xs[];   // [1024][20]
    int t = threadIdx.x;
    int k0 = blockIdx.x << 10;
    int KN = KDIM - k0; if (KN > 1024) KN = 1024;

    for (int idx = t; idx < 4096; idx += 256) {
        int b  = idx & 15;
        int kk = (idx >> 4) << 2;
        float4 v = make_float4(0.f, 0.f, 0.f, 0.f);
        if (kk < KN)
            v = *reinterpret_cast<const float4*>(x2 + (size_t)b * KDIM + k0 + kk);
        xs[(kk + 0) * 20 + b] = v.x;
        xs[(kk + 1) * 20 + b] = v.y;
        xs[(kk + 2) * 20 + b] = v.z;
        xs[(kk + 3) * 20 + b] = v.w;
    }
    __syncthreads();

    int wid = t >> 5, lane = t & 31;
    int o0 = (blockIdx.y << 5) + (wid << 2);
    if (o0 >= O1) return;

    double acc2[4][8];
#pragma unroll
    for (int o = 0; o < 4; o++)
#pragma unroll
        for (int bp = 0; bp < 8; bp++) acc2[o][bp] = 0.0;

    const float* wbase = W + (size_t)o0 * KDIM + k0;

    // 4-deep W prefetch (unchanged)
    float wbuf[4][4];
#pragma unroll
    for (int p = 0; p < 4; p++) {
        int k = lane + (p << 5);
#pragma unroll
        for (int o = 0; o < 4; o++)
            wbuf[p][o] = (k < KN) ? __ldg(wbase + (size_t)o * KDIM + k) : 0.0f;
    }

    // x pipeline prologue: first half of iteration 0
    double2 xA, xB;
    {
        const double2* xr0 = reinterpret_cast<const double2*>(&xs[lane * 20]);
        xA = xr0[0]; xB = xr0[1];
    }

#pragma unroll 4
    for (int it = 0; it < 32; it++) {
        int slot = it & 3;
        int k = lane + (it << 5);

        double wd[4];
#pragma unroll
        for (int o = 0; o < 4; o++) wd[o] = pk2(wbuf[slot][o], wbuf[slot][o]);

        // refill W slot for it+4 (long distance for DRAM latency)
        int kn = k + 128;
#pragma unroll
        for (int o = 0; o < 4; o++)
            wbuf[slot][o] = (kn < KN) ? __ldg(wbase + (size_t)o * KDIM + kn) : 0.0f;

        // load SECOND half of this iteration now (consumed after 16 FFMA2 > 29cyc)
        const double2* xr = reinterpret_cast<const double2*>(&xs[k * 20]);
        double2 xC = xr[2], xD = xr[3];

        // FMA first half (bp 0..3) on prefetched xA,xB
        {
            double xp0[4] = {xA.x, xA.y, xB.x, xB.y};
#pragma unroll
            for (int o = 0; o < 4; o++)
#pragma unroll
                for (int bp = 0; bp < 4; bp++)
                    acc2[o][bp] = ffma2(wd[o], xp0[bp], acc2[o][bp]);
        }

        // prefetch FIRST half of next iteration (consumed after 16 FFMA2)
        if (it < 31) {
            const double2* xrn = reinterpret_cast<const double2*>(&xs[(k + 32) * 20]);
            xA = xrn[0]; xB = xrn[1];
        }

        // FMA second half (bp 4..7)
        {
            double xp1[4] = {xC.x, xC.y, xD.x, xD.y};
#pragma unroll
            for (int o = 0; o < 4; o++)
#pragma unroll
                for (int bp = 0; bp < 4; bp++)
                    acc2[o][bp + 4] = ffma2(wd[o], xp1[bp], acc2[o][bp + 4]);
        }
    }

    // butterfly reduce (packed adds) — unchanged
    double s2[32];
#pragma unroll
    for (int a = 0; a < 32; a++) s2[a] = acc2[a >> 3][a & 7];
    int n = 32;
#pragma unroll
    for (int d = 16; d >= 1; d >>= 1) {
        n >>= 1;
        bool hiSel = (lane & d) != 0;
#pragma unroll
        for (int i = 0; i < 16; i++) {
            if (i >= n) break;
            double send = hiSel ? s2[i] : s2[i + n];
            double recv = __shfl_xor_sync(0xffffffffu, send, d);
            double keep = hiSel ? s2[i + n] : s2[i];
            s2[i] = fadd2(keep, recv);
        }
    }
    float lo, hi; upk2(s2[0], lo, hi);
    float* addr = &g_y1[(o0 + (lane >> 3)) * 16 + 2 * (lane & 7)];
    asm volatile("red.global.add.v2.f32 [%0], {%1, %2};"
                 :: "l"(addr), "f"(lo), "f"(hi) : "memory");
}

// ---------------- dense2 + softmax ----------------
__global__ void dense2_kernel(const float* __restrict__ Wd2, float* __restrict__ out) {
    __shared__ float ys[O1];
    __shared__ float red[128];
    int b = blockIdx.x, t = threadIdx.x;
    for (int o = t; o < O1; o += 128) ys[o] = fmaxf(g_y1[o * 16 + b], 0.0f);
    __syncthreads();

    float logit = -1e30f;
    if (t < NCLS) {
        float s = 0.0f;
        const float* wr = Wd2 + t * O1;
        for (int o = 0; o < O1; o++) s = fmaf(ys[o], __ldg(wr + o), s);
        logit = s;
    }
    red[t] = logit;
    __syncthreads();
    for (int s = 64; s > 0; s >>= 1) {
        if (t < s) red[t] = fmaxf(red[t], red[t + s]);
        __syncthreads();
    }
    float mx = red[0];
    __syncthreads();
    float e = (t < NCLS) ? expf(logit - mx) : 0.0f;
    red[t] = e;
    __syncthreads();
    for (int s = 64; s > 0; s >>= 1) {
        if (t < s) red[t] += red[t + s];
        __syncthreads();
    }
    float sum = red[0];
    if (t < NCLS) out[b * NCLS + t] = e / sum;
}

// ---------------- launch ----------------
extern "C" void kernel_launch(void* const* d_in, const int* in_sizes, int n_in,
                              void* d_out, int out_size) {
    const float* x_src = (const float*)d_in[0];
    const float* x_dst = (const float*)d_in[1];
    const int*   ei    = (const int*)  d_in[2];
    const float* Wfd   = (const float*)d_in[3];
    const float* bfd   = (const float*)d_in[4];
    const float* Wl1   = (const float*)d_in[5];
    const float* bl1   = (const float*)d_in[6];
    const float* Wr1   = (const float*)d_in[7];
    const float* Wc1   = (const float*)d_in[11];
    const float* Wc2   = (const float*)d_in[12];
    const float* Wd1   = (const float*)d_in[13];
    const float* Wd2   = (const float*)d_in[14];
    float* out = (float*)d_out;

    float *p_xp, *p_o1, *p_o2;
    cudaGetSymbolAddress((void**)&p_xp, g_xp);
    cudaGetSymbolAddress((void**)&p_o1, g_out1);
    cudaGetSymbolAddress((void**)&p_o2, g_out2);

    cudaFuncSetAttribute(feat_kernel,   cudaFuncAttributeMaxDynamicSharedMemorySize, FEAT_SMEM);
    cudaFuncSetAttribute(conv_kernel,   cudaFuncAttributeMaxDynamicSharedMemorySize, CONV_SMEM);
    cudaFuncSetAttribute(conv_kernel,   cudaFuncAttributePreferredSharedMemoryCarveout, 100);
    cudaFuncSetAttribute(dense1_kernel, cudaFuncAttributeMaxDynamicSharedMemorySize, D1_SMEM);
    cudaFuncSetAttribute(dense1_kernel, cudaFuncAttributePreferredSharedMemoryCarveout, 100);

    zero_kernel<<<(N_P * 4 + 255) / 256, 256>>>();
    feat_kernel<<<128, 256, FEAT_SMEM>>>(x_src, Wfd, bfd);
    edge_kernel<<<4096, 256>>>(ei);
    node_kernel<<<6400, 256>>>(x_dst, Wl1, bl1, Wr1);
    conv_kernel<<<dim3(16, 64), 200, CONV_SMEM>>>(p_xp, Wc1, p_o1, L0, L1V);
    conv_kernel<<<dim3(16, 64), 200, CONV_SMEM>>>(p_o1, Wc2, p_o2, L1V, L2V);
    dense1_kernel<<<dim3(400, 16), 256, D1_SMEM>>>(p_o2, Wd1);
    dense2_kernel<<<NB, 128>>>(Wd2, out);
}

// round 15
// speedup vs baseline: 1.1361x; 1.0814x over previous
#include <cuda_runtime.h>
#include <cstdint>

// ---------------- problem constants ----------------
#define NB       16
#define N_F      524288
#define N_P      65536
#define EH       2097152
#define E_TOTAL  4194304
#define XP_N     6553600
#define L0       4096
#define L1V      4095
#define L2V      4094
#define KDIM     409400
#define O1       500
#define NCLS     107

// ---------------- packed fp32x2 helpers ----------------
__device__ __forceinline__ double pk2(float lo, float hi) {
    double d; asm("mov.b64 %0, {%1, %2};" : "=d"(d) : "f"(lo), "f"(hi)); return d;
}
__device__ __forceinline__ void upk2(double d, float& lo, float& hi) {
    asm("mov.b64 {%0, %1}, %2;" : "=f"(lo), "=f"(hi) : "d"(d));
}
__device__ __forceinline__ double ffma2(double a, double b, double c) {
    double d; asm("fma.rn.f32x2 %0, %1, %2, %3;" : "=d"(d) : "d"(a), "d"(b), "d"(c)); return d;
}
__device__ __forceinline__ double fadd2(double a, double b) {
    double d; asm("add.rn.f32x2 %0, %1, %2;" : "=d"(d) : "d"(a), "d"(b)); return d;
}

// ---------------- scratch ----------------
__device__ float4 g_xf4[N_F];
__device__ float g_agg[N_P * 4];
__device__ float g_xp[XP_N];
__device__ float g_out1[NB * 100 * L1V];
__device__ float g_out2[NB * 100 * L2V];
__device__ float g_y1[O1 * NB];

// ---------------- feat (+ fused zero init): 8192x64 @ 64x192 -> g_xf4 ------------
#define FEAT_SMEM ((64 * 65 + 192 * 65) * 4)
__global__ __launch_bounds__(256)
void feat_kernel(const float* __restrict__ xsrc,
                 const float* __restrict__ Wfd,
                 const float* __restrict__ bfd) {
    int t0 = blockIdx.x * 256 + threadIdx.x;   // 32768 threads
#pragma unroll
    for (int z = t0; z < N_P * 4; z += 32768) g_agg[z] = 0.0f;
    if (t0 < O1 * NB) g_y1[t0] = 0.0f;

    extern __shared__ float sm[];
    float* xs = sm;             // [64][65]
    float* ws = sm + 64 * 65;   // [192][65]
    int t = threadIdx.x;
    int i0 = blockIdx.x << 6;

    for (int idx = t; idx < 4096; idx += 256) {
        int i = idx >> 6, k = idx & 63;
        xs[i * 65 + k] = xsrc[(i0 + i) * 64 + k];
    }
    for (int idx = t; idx < 12288; idx += 256) {
        int j = idx >> 6, k = idx & 63;
        ws[j * 65 + k] = Wfd[idx];
    }
    __syncthreads();

    int tx = t & 15, ty = t >> 4;
    float acc[4][12];
#pragma unroll
    for (int ii = 0; ii < 4; ii++)
#pragma unroll
        for (int jj = 0; jj < 12; jj++) acc[ii][jj] = 0.0f;

    for (int k = 0; k < 64; k++) {
        float xv[4], wv[12];
#pragma unroll
        for (int ii = 0; ii < 4; ii++) xv[ii] = xs[(ty * 4 + ii) * 65 + k];
#pragma unroll
        for (int jj = 0; jj < 12; jj++) wv[jj] = ws[(tx * 12 + jj) * 65 + k];
#pragma unroll
        for (int ii = 0; ii < 4; ii++)
#pragma unroll
            for (int jj = 0; jj < 12; jj++)
                acc[ii][jj] = fmaf(xv[ii], wv[jj], acc[ii][jj]);
    }

    int j0 = tx * 12;
#pragma unroll
    for (int ii = 0; ii < 4; ii++) {
        int i = i0 + ty * 4 + ii;
#pragma unroll
        for (int rr = 0; rr < 4; rr++) {
            int r = i * 64 + tx * 4 + rr;
            g_xf4[r] = make_float4(
                acc[ii][rr * 3 + 0] + __ldg(bfd + j0 + rr * 3 + 0),
                acc[ii][rr * 3 + 1] + __ldg(bfd + j0 + rr * 3 + 1),
                acc[ii][rr * 3 + 2] + __ldg(bfd + j0 + rr * 3 + 2),
                0.0f);
        }
    }
}

// ---------------- edge aggregation ----------------
__global__ void edge_kernel(const int* __restrict__ ei) {
    int e2 = blockIdx.x * 256 + threadIdx.x;
    int4 s4 = *reinterpret_cast<const int4*>(ei + 4 * e2);
    int4 d4 = *reinterpret_cast<const int4*>(ei + E_TOTAL + 4 * e2);
    float4 v0 = g_xf4[s4.x];
    float4 v1 = g_xf4[s4.z];
    float* a0 = g_agg + 4 * d4.x;
    float* a1 = g_agg + 4 * d4.z;
    asm volatile("red.global.add.v4.f32 [%0], {%1, %2, %3, %4};"
                 :: "l"(a0), "f"(v0.x), "f"(v0.y), "f"(v0.z), "f"(1.0f) : "memory");
    asm volatile("red.global.add.v4.f32 [%0], {%1, %2, %3, %4};"
                 :: "l"(a1), "f"(v1.x), "f"(v1.y), "f"(v1.z), "f"(1.0f) : "memory");
}

// ---------------- node update (R7-proven) ----------------
__global__ __launch_bounds__(256)
void node_kernel(const float* __restrict__ xdst,
                 const float* __restrict__ Wl1,
                 const float* __restrict__ bl1,
                 const float* __restrict__ Wr1) {
    __shared__ float swl[300], swr[300], sb[100];
    int t = threadIdx.x;
    for (int idx = t; idx < 300; idx += 256) { swl[idx] = Wl1[idx]; swr[idx] = Wr1[idx]; }
    if (t < 100) sb[t] = bl1[t];
    __syncthreads();

    int gid = blockIdx.x * 256 + t;
    int n = gid / 25;
    int c0 = (gid - n * 25) * 4;
    float4 a = *reinterpret_cast<const float4*>(&g_agg[n * 4]);
    float inv = __fdividef(1.0f, fmaxf(a.w, 1.0f));
    float m0 = a.x * inv, m1 = a.y * inv, m2 = a.z * inv;
    const float* xd = xdst + 3 * n;
    float d0 = xd[0], d1 = xd[1], d2 = xd[2];
    float r[4];
#pragma unroll
    for (int cc = 0; cc < 4; cc++) {
        int c = c0 + cc;
        float v = sb[c];
        v = fmaf(m0, swl[c * 3 + 0], v);
        v = fmaf(m1, swl[c * 3 + 1], v);
        v = fmaf(m2, swl[c * 3 + 2], v);
        v = fmaf(d0, swr[c * 3 + 0], v);
        v = fmaf(d1, swr[c * 3 + 1], v);
        v = fmaf(d2, swr[c * 3 + 2], v);
        r[cc] = fmaxf(v, 0.0f);
    }
    *reinterpret_cast<float4*>(&g_xp[n * 100 + c0]) =
        make_float4(r[0], r[1], r[2], r[3]);
}

// ---------------- conv: 400 threads, h-tile 128, same inner loop -----------------
// block 400 = 25 og x 16 ht. ws [100][202] 80.8KB + xs [100][132] 52.8KB = 133.6KB.
// 12.5 warps/SM (3.1/SMSP) vs 6.25 before -> LDS latency overlap doubles.
#define CONV_SMEM ((100 * 202 + 100 * 132) * 4)
__global__ __launch_bounds__(400)
void conv_kernel(const float* __restrict__ in, const float* __restrict__ W,
                 float* __restrict__ out, int Lin, int Lout) {
    extern __shared__ float sm[];
    float* ws = sm;               // [o][202]
    float* xs = sm + 100 * 202;   // [i][132]
    int b  = blockIdx.x;
    int h0 = blockIdx.y << 7;     // h-tile 128
    int t  = threadIdx.x;

    for (int idx = t; idx < 20000; idx += 400) {
        int o = idx / 200;
        ws[o * 202 + (idx - o * 200)] = W[idx];
    }
    int nj = Lin - h0; if (nj > 129) nj = 129;
    const float* inb = in + b * 100 * Lin + h0;
    for (int idx = t; idx < 13200; idx += 400) {
        int i = idx / 132;
        int j = idx - i * 132;
        xs[idx] = (j < nj) ? inb[i * Lin + j] : 0.0f;
    }
    __syncthreads();

    int og = t >> 4, ht = t & 15;
    int o0 = og << 2, hh = ht << 3;
    double acc2[4][8];
#pragma unroll
    for (int oo = 0; oo < 4; oo++)
#pragma unroll
        for (int j = 0; j < 8; j++) acc2[oo][j] = 0.0;

    for (int i = 0; i < 100; i++) {
        const float* xr = xs + i * 132 + hh;
        float4 xA = *reinterpret_cast<const float4*>(xr);
        float4 xB = *reinterpret_cast<const float4*>(xr + 4);
        float x8 = xr[8];
        double xp[8];
        xp[0] = pk2(xA.x, xA.y); xp[1] = pk2(xA.y, xA.z);
        xp[2] = pk2(xA.z, xA.w); xp[3] = pk2(xA.w, xB.x);
        xp[4] = pk2(xB.x, xB.y); xp[5] = pk2(xB.y, xB.z);
        xp[6] = pk2(xB.z, xB.w); xp[7] = pk2(xB.w, x8);
#pragma unroll
        for (int oo = 0; oo < 4; oo++) {
            double wp = *reinterpret_cast<const double*>(&ws[(o0 + oo) * 202 + i * 2]);
#pragma unroll
            for (int j = 0; j < 8; j++)
                acc2[oo][j] = ffma2(wp, xp[j], acc2[oo][j]);
        }
    }

    float* outb = out + b * 100 * Lout;
#pragma unroll
    for (int oo = 0; oo < 4; oo++)
#pragma unroll
        for (int j = 0; j < 8; j++) {
            int h = h0 + hh + j;
            if (h < Lout) {
                float lo, hi; upk2(acc2[oo][j], lo, hi);
                outb[(o0 + oo) * Lout + h] = fmaxf(lo + hi, 0.0f);
            }
        }
}

// ---------------- dense1 v4 (655us champion, verbatim) ----------------
#define D1_SMEM (1024 * 20 * 4)
__global__ __launch_bounds__(256, 2)
void dense1_kernel(const float* __restrict__ x2, const float* __restrict__ W) {
    extern __shared__ float xs[];   // [1024][20]
    int t = threadIdx.x;
    int k0 = blockIdx.x << 10;
    int KN = KDIM - k0; if (KN > 1024) KN = 1024;

    for (int idx = t; idx < 4096; idx += 256) {
        int b  = idx & 15;
        int kk = (idx >> 4) << 2;
        float4 v = make_float4(0.f, 0.f, 0.f, 0.f);
        if (kk < KN)
            v = *reinterpret_cast<const float4*>(x2 + (size_t)b * KDIM + k0 + kk);
        xs[(kk + 0) * 20 + b] = v.x;
        xs[(kk + 1) * 20 + b] = v.y;
        xs[(kk + 2) * 20 + b] = v.z;
        xs[(kk + 3) * 20 + b] = v.w;
    }
    __syncthreads();

    int wid = t >> 5, lane = t & 31;
    int o0 = (blockIdx.y << 5) + (wid << 2);
    if (o0 >= O1) return;

    double acc2[4][8];
#pragma unroll
    for (int o = 0; o < 4; o++)
#pragma unroll
        for (int bp = 0; bp < 8; bp++) acc2[o][bp] = 0.0;

    const float* wbase = W + (size_t)o0 * KDIM + k0;

    float wbuf[4][4];
#pragma unroll
    for (int p = 0; p < 4; p++) {
        int k = lane + (p << 5);
#pragma unroll
        for (int o = 0; o < 4; o++)
            wbuf[p][o] = (k < KN) ? __ldg(wbase + (size_t)o * KDIM + k) : 0.0f;
    }

#pragma unroll 4
    for (int it = 0; it < 32; it++) {
        int slot = it & 3;
        int k = lane + (it << 5);

        double wd[4];
#pragma unroll
        for (int o = 0; o < 4; o++) wd[o] = pk2(wbuf[slot][o], wbuf[slot][o]);

        int kn = k + 128;
#pragma unroll
        for (int o = 0; o < 4; o++)
            wbuf[slot][o] = (kn < KN) ? __ldg(wbase + (size_t)o * KDIM + kn) : 0.0f;

        const double2* xrow = reinterpret_cast<const double2*>(&xs[k * 20]);
        double2 x01 = xrow[0], x23 = xrow[1], x45 = xrow[2], x67 = xrow[3];
        double xp[8] = {x01.x, x01.y, x23.x, x23.y, x45.x, x45.y, x67.x, x67.y};

#pragma unroll
        for (int o = 0; o < 4; o++)
#pragma unroll
            for (int bp = 0; bp < 8; bp++)
                acc2[o][bp] = ffma2(wd[o], xp[bp], acc2[o][bp]);
    }

    double s2[32];
#pragma unroll
    for (int a = 0; a < 32; a++) s2[a] = acc2[a >> 3][a & 7];
    int n = 32;
#pragma unroll
    for (int d = 16; d >= 1; d >>= 1) {
        n >>= 1;
        bool hiSel = (lane & d) != 0;
#pragma unroll
        for (int i = 0; i < 16; i++) {
            if (i >= n) break;
            double send = hiSel ? s2[i] : s2[i + n];
            double recv = __shfl_xor_sync(0xffffffffu, send, d);
            double keep = hiSel ? s2[i + n] : s2[i];
            s2[i] = fadd2(keep, recv);
        }
    }
    float lo, hi; upk2(s2[0], lo, hi);
    float* addr = &g_y1[(o0 + (lane >> 3)) * 16 + 2 * (lane & 7)];
    asm volatile("red.global.add.v2.f32 [%0], {%1, %2};"
                 :: "l"(addr), "f"(lo), "f"(hi) : "memory");
}

// ---------------- dense2 + softmax ----------------
__global__ void dense2_kernel(const float* __restrict__ Wd2, float* __restrict__ out) {
    __shared__ float ys[O1];
    __shared__ float red[128];
    int b = blockIdx.x, t = threadIdx.x;
    for (int o = t; o < O1; o += 128) ys[o] = fmaxf(g_y1[o * 16 + b], 0.0f);
    __syncthreads();

    float logit = -1e30f;
    if (t < NCLS) {
        float s = 0.0f;
        const float* wr = Wd2 + t * O1;
        for (int o = 0; o < O1; o++) s = fmaf(ys[o], __ldg(wr + o), s);
        logit = s;
    }
    red[t] = logit;
    __syncthreads();
    for (int s = 64; s > 0; s >>= 1) {
        if (t < s) red[t] = fmaxf(red[t], red[t + s]);
        __syncthreads();
    }
    float mx = red[0];
    __syncthreads();
    float e = (t < NCLS) ? expf(logit - mx) : 0.0f;
    red[t] = e;
    __syncthreads();
    for (int s = 64; s > 0; s >>= 1) {
        if (t < s) red[t] += red[t + s];
        __syncthreads();
    }
    float sum = red[0];
    if (t < NCLS) out[b * NCLS + t] = e / sum;
}

// ---------------- launch ----------------
extern "C" void kernel_launch(void* const* d_in, const int* in_sizes, int n_in,
                              void* d_out, int out_size) {
    const float* x_src = (const float*)d_in[0];
    const float* x_dst = (const float*)d_in[1];
    const int*   ei    = (const int*)  d_in[2];
    const float* Wfd   = (const float*)d_in[3];
    const float* bfd   = (const float*)d_in[4];
    const float* Wl1   = (const float*)d_in[5];
    const float* bl1   = (const float*)d_in[6];
    const float* Wr1   = (const float*)d_in[7];
    const float* Wc1   = (const float*)d_in[11];
    const float* Wc2   = (const float*)d_in[12];
    const float* Wd1   = (const float*)d_in[13];
    const float* Wd2   = (const float*)d_in[14];
    float* out = (float*)d_out;

    float *p_xp, *p_o1, *p_o2;
    cudaGetSymbolAddress((void**)&p_xp, g_xp);
    cudaGetSymbolAddress((void**)&p_o1, g_out1);
    cudaGetSymbolAddress((void**)&p_o2, g_out2);

    cudaFuncSetAttribute(feat_kernel,   cudaFuncAttributeMaxDynamicSharedMemorySize, FEAT_SMEM);
    cudaFuncSetAttribute(conv_kernel,   cudaFuncAttributeMaxDynamicSharedMemorySize, CONV_SMEM);
    cudaFuncSetAttribute(dense1_kernel, cudaFuncAttributeMaxDynamicSharedMemorySize, D1_SMEM);

    feat_kernel<<<128, 256, FEAT_SMEM>>>(x_src, Wfd, bfd);                 // #1 (+zero)
    edge_kernel<<<4096, 256>>>(ei);                                        // #2
    node_kernel<<<6400, 256>>>(x_dst, Wl1, bl1, Wr1);                      // #3
    conv_kernel<<<dim3(16, 32), 400, CONV_SMEM>>>(p_xp, Wc1, p_o1, L0, L1V);   // #4
    conv_kernel<<<dim3(16, 32), 400, CONV_SMEM>>>(p_o1, Wc2, p_o2, L1V, L2V);  // #5
    dense1_kernel<<<dim3(400, 16), 256, D1_SMEM>>>(p_o2, Wd1);             // #6
    dense2_kernel<<<NB, 128>>>(Wd2, out);                                  // #7
}

// round 16
// speedup vs baseline: 1.2042x; 1.0600x over previous
#include <cuda_runtime.h>
#include <cstdint>

// ---------------- problem constants ----------------
#define NB       16
#define N_F      524288
#define N_P      65536
#define EH       2097152
#define E_TOTAL  4194304
#define XP_N     6553600
#define L0       4096
#define L1V      4095
#define L2V      4094
#define KDIM     409400
#define O1       500
#define NCLS     107

// ---------------- packed fp32x2 helpers ----------------
__device__ __forceinline__ double pk2(float lo, float hi) {
    double d; asm("mov.b64 %0, {%1, %2};" : "=d"(d) : "f"(lo), "f"(hi)); return d;
}
__device__ __forceinline__ void upk2(double d, float& lo, float& hi) {
    asm("mov.b64 {%0, %1}, %2;" : "=f"(lo), "=f"(hi) : "d"(d));
}
__device__ __forceinline__ double ffma2(double a, double b, double c) {
    double d; asm("fma.rn.f32x2 %0, %1, %2, %3;" : "=d"(d) : "d"(a), "d"(b), "d"(c)); return d;
}
__device__ __forceinline__ double fadd2(double a, double b) {
    double d; asm("add.rn.f32x2 %0, %1, %2;" : "=d"(d) : "d"(a), "d"(b)); return d;
}

// ---------------- scratch ----------------
__device__ float4 g_xf4[N_F];
__device__ float g_agg[N_P * 4];
__device__ float g_xp[XP_N];
__device__ float g_out1[NB * 100 * L1V];
__device__ float g_out2[NB * 100 * L2V];
__device__ float g_y1[O1 * NB];

// ---------------- feat (+ fused zero init) ----------------
#define FEAT_SMEM ((64 * 65 + 192 * 65) * 4)
__global__ __launch_bounds__(256)
void feat_kernel(const float* __restrict__ xsrc,
                 const float* __restrict__ Wfd,
                 const float* __restrict__ bfd) {
    int t0 = blockIdx.x * 256 + threadIdx.x;
#pragma unroll
    for (int z = t0; z < N_P * 4; z += 32768) g_agg[z] = 0.0f;
    if (t0 < O1 * NB) g_y1[t0] = 0.0f;

    extern __shared__ float sm[];
    float* xs = sm;             // [64][65]
    float* ws = sm + 64 * 65;   // [192][65]
    int t = threadIdx.x;
    int i0 = blockIdx.x << 6;

    for (int idx = t; idx < 4096; idx += 256) {
        int i = idx >> 6, k = idx & 63;
        xs[i * 65 + k] = xsrc[(i0 + i) * 64 + k];
    }
    for (int idx = t; idx < 12288; idx += 256) {
        int j = idx >> 6, k = idx & 63;
        ws[j * 65 + k] = Wfd[idx];
    }
    __syncthreads();

    int tx = t & 15, ty = t >> 4;
    float acc[4][12];
#pragma unroll
    for (int ii = 0; ii < 4; ii++)
#pragma unroll
        for (int jj = 0; jj < 12; jj++) acc[ii][jj] = 0.0f;

    for (int k = 0; k < 64; k++) {
        float xv[4], wv[12];
#pragma unroll
        for (int ii = 0; ii < 4; ii++) xv[ii] = xs[(ty * 4 + ii) * 65 + k];
#pragma unroll
        for (int jj = 0; jj < 12; jj++) wv[jj] = ws[(tx * 12 + jj) * 65 + k];
#pragma unroll
        for (int ii = 0; ii < 4; ii++)
#pragma unroll
            for (int jj = 0; jj < 12; jj++)
                acc[ii][jj] = fmaf(xv[ii], wv[jj], acc[ii][jj]);
    }

    int j0 = tx * 12;
#pragma unroll
    for (int ii = 0; ii < 4; ii++) {
        int i = i0 + ty * 4 + ii;
#pragma unroll
        for (int rr = 0; rr < 4; rr++) {
            int r = i * 64 + tx * 4 + rr;
            g_xf4[r] = make_float4(
                acc[ii][rr * 3 + 0] + __ldg(bfd + j0 + rr * 3 + 0),
                acc[ii][rr * 3 + 1] + __ldg(bfd + j0 + rr * 3 + 1),
                acc[ii][rr * 3 + 2] + __ldg(bfd + j0 + rr * 3 + 2),
                0.0f);
        }
    }
}

// ---------------- edge aggregation ----------------
__global__ void edge_kernel(const int* __restrict__ ei) {
    int e2 = blockIdx.x * 256 + threadIdx.x;
    int4 s4 = *reinterpret_cast<const int4*>(ei + 4 * e2);
    int4 d4 = *reinterpret_cast<const int4*>(ei + E_TOTAL + 4 * e2);
    float4 v0 = g_xf4[s4.x];
    float4 v1 = g_xf4[s4.z];
    float* a0 = g_agg + 4 * d4.x;
    float* a1 = g_agg + 4 * d4.z;
    asm volatile("red.global.add.v4.f32 [%0], {%1, %2, %3, %4};"
                 :: "l"(a0), "f"(v0.x), "f"(v0.y), "f"(v0.z), "f"(1.0f) : "memory");
    asm volatile("red.global.add.v4.f32 [%0], {%1, %2, %3, %4};"
                 :: "l"(a1), "f"(v1.x), "f"(v1.y), "f"(v1.z), "f"(1.0f) : "memory");
}

// ---------------- node update ----------------
__global__ __launch_bounds__(256)
void node_kernel(const float* __restrict__ xdst,
                 const float* __restrict__ Wl1,
                 const float* __restrict__ bl1,
                 const float* __restrict__ Wr1) {
    __shared__ float swl[300], swr[300], sb[100];
    int t = threadIdx.x;
    for (int idx = t; idx < 300; idx += 256) { swl[idx] = Wl1[idx]; swr[idx] = Wr1[idx]; }
    if (t < 100) sb[t] = bl1[t];
    __syncthreads();

    int gid = blockIdx.x * 256 + t;
    int n = gid / 25;
    int c0 = (gid - n * 25) * 4;
    float4 a = *reinterpret_cast<const float4*>(&g_agg[n * 4]);
    float inv = __fdividef(1.0f, fmaxf(a.w, 1.0f));
    float m0 = a.x * inv, m1 = a.y * inv, m2 = a.z * inv;
    const float* xd = xdst + 3 * n;
    float d0 = xd[0], d1 = xd[1], d2 = xd[2];
    float r[4];
#pragma unroll
    for (int cc = 0; cc < 4; cc++) {
        int c = c0 + cc;
        float v = sb[c];
        v = fmaf(m0, swl[c * 3 + 0], v);
        v = fmaf(m1, swl[c * 3 + 1], v);
        v = fmaf(m2, swl[c * 3 + 2], v);
        v = fmaf(d0, swr[c * 3 + 0], v);
        v = fmaf(d1, swr[c * 3 + 1], v);
        v = fmaf(d2, swr[c * 3 + 2], v);
        r[cc] = fmaxf(v, 0.0f);
    }
    *reinterpret_cast<float4*>(&g_xp[n * 100 + c0]) =
        make_float4(r[0], r[1], r[2], r[3]);
}

// ---------------- conv: champion config + x-register prefetch pipeline -----------
// 200 thr, h-tile 64, 2 blocks/SM. No launch_bounds reg cap -> no spill risk.
#define CONV_SMEM ((100 * 202 + 100 * 68) * 4)
__global__ __launch_bounds__(200)
void conv_kernel(const float* __restrict__ in, const float* __restrict__ W,
                 float* __restrict__ out, int Lin, int Lout) {
    extern __shared__ float sm[];
    float* ws = sm;               // [o][202]
    float* xs = sm + 100 * 202;   // [i][68]
    int b  = blockIdx.x;
    int h0 = blockIdx.y << 6;
    int t  = threadIdx.x;

    for (int idx = t; idx < 20000; idx += 200) {
        int o = idx / 200;
        ws[o * 202 + (idx - o * 200)] = W[idx];
    }
    int nj = Lin - h0; if (nj > 65) nj = 65;
    const float* inb = in + b * 100 * Lin + h0;
    for (int idx = t; idx < 6800; idx += 200) {
        int i = idx / 68;
        int j = idx - i * 68;
        xs[idx] = (j < nj) ? inb[i * Lin + j] : 0.0f;
    }
    __syncthreads();

    int og = t >> 3, ht = t & 7;
    int o0 = og << 2, hh = ht << 3;
    double acc2[4][8];
#pragma unroll
    for (int oo = 0; oo < 4; oo++)
#pragma unroll
        for (int j = 0; j < 8; j++) acc2[oo][j] = 0.0;

    // prologue: x row for i=0
    float4 xA, xB; float x8;
    {
        const float* xr = xs + hh;
        xA = *reinterpret_cast<const float4*>(xr);
        xB = *reinterpret_cast<const float4*>(xr + 4);
        x8 = xr[8];
    }

    for (int i = 0; i < 100; i++) {
        // build pairs from prefetched registers
        double xp[8];
        xp[0] = pk2(xA.x, xA.y); xp[1] = pk2(xA.y, xA.z);
        xp[2] = pk2(xA.z, xA.w); xp[3] = pk2(xA.w, xB.x);
        xp[4] = pk2(xB.x, xB.y); xp[5] = pk2(xB.y, xB.z);
        xp[6] = pk2(xB.z, xB.w); xp[7] = pk2(xB.w, x8);

        // FMAs for oo = 0,1
#pragma unroll
        for (int oo = 0; oo < 2; oo++) {
            double wp = *reinterpret_cast<const double*>(&ws[(o0 + oo) * 202 + i * 2]);
#pragma unroll
            for (int j = 0; j < 8; j++)
                acc2[oo][j] = ffma2(wp, xp[j], acc2[oo][j]);
        }

        // prefetch x row for i+1 (consumed after >=16 FFMA2 -> 29cyc LDS hidden)
        if (i < 99) {
            const float* xrn = xs + (i + 1) * 68 + hh;
            xA = *reinterpret_cast<const float4*>(xrn);
            xB = *reinterpret_cast<const float4*>(xrn + 4);
            x8 = xrn[8];
        }

        // FMAs for oo = 2,3
#pragma unroll
        for (int oo = 2; oo < 4; oo++) {
            double wp = *reinterpret_cast<const double*>(&ws[(o0 + oo) * 202 + i * 2]);
#pragma unroll
            for (int j = 0; j < 8; j++)
                acc2[oo][j] = ffma2(wp, xp[j], acc2[oo][j]);
        }
    }

    float* outb = out + b * 100 * Lout;
#pragma unroll
    for (int oo = 0; oo < 4; oo++)
#pragma unroll
        for (int j = 0; j < 8; j++) {
            int h = h0 + hh + j;
            if (h < Lout) {
                float lo, hi; upk2(acc2[oo][j], lo, hi);
                outb[(o0 + oo) * Lout + h] = fmaxf(lo + hi, 0.0f);
            }
        }
}

// ---------------- dense1 v4 (champion, verbatim) ----------------
#define D1_SMEM (1024 * 20 * 4)
__global__ __launch_bounds__(256, 2)
void dense1_kernel(const float* __restrict__ x2, const float* __restrict__ W) {
    extern __shared__ float xs[];   // [1024][20]
    int t = threadIdx.x;
    int k0 = blockIdx.x << 10;
    int KN = KDIM - k0; if (KN > 1024) KN = 1024;

    for (int idx = t; idx < 4096; idx += 256) {
        int b  = idx & 15;
        int kk = (idx >> 4) << 2;
        float4 v = make_float4(0.f, 0.f, 0.f, 0.f);
        if (kk < KN)
            v = *reinterpret_cast<const float4*>(x2 + (size_t)b * KDIM + k0 + kk);
        xs[(kk + 0) * 20 + b] = v.x;
        xs[(kk + 1) * 20 + b] = v.y;
        xs[(kk + 2) * 20 + b] = v.z;
        xs[(kk + 3) * 20 + b] = v.w;
    }
    __syncthreads();

    int wid = t >> 5, lane = t & 31;
    int o0 = (blockIdx.y << 5) + (wid << 2);
    if (o0 >= O1) return;

    double acc2[4][8];
#pragma unroll
    for (int o = 0; o < 4; o++)
#pragma unroll
        for (int bp = 0; bp < 8; bp++) acc2[o][bp] = 0.0;

    const float* wbase = W + (size_t)o0 * KDIM + k0;

    float wbuf[4][4];
#pragma unroll
    for (int p = 0; p < 4; p++) {
        int k = lane + (p << 5);
#pragma unroll
        for (int o = 0; o < 4; o++)
            wbuf[p][o] = (k < KN) ? __ldg(wbase + (size_t)o * KDIM + k) : 0.0f;
    }

#pragma unroll 4
    for (int it = 0; it < 32; it++) {
        int slot = it & 3;
        int k = lane + (it << 5);

        double wd[4];
#pragma unroll
        for (int o = 0; o < 4; o++) wd[o] = pk2(wbuf[slot][o], wbuf[slot][o]);

        int kn = k + 128;
#pragma unroll
        for (int o = 0; o < 4; o++)
            wbuf[slot][o] = (kn < KN) ? __ldg(wbase + (size_t)o * KDIM + kn) : 0.0f;

        const double2* xrow = reinterpret_cast<const double2*>(&xs[k * 20]);
        double2 x01 = xrow[0], x23 = xrow[1], x45 = xrow[2], x67 = xrow[3];
        double xp[8] = {x01.x, x01.y, x23.x, x23.y, x45.x, x45.y, x67.x, x67.y};

#pragma unroll
        for (int o = 0; o < 4; o++)
#pragma unroll
            for (int bp = 0; bp < 8; bp++)
                acc2[o][bp] = ffma2(wd[o], xp[bp], acc2[o][bp]);
    }

    double s2[32];
#pragma unroll
    for (int a = 0; a < 32; a++) s2[a] = acc2[a >> 3][a & 7];
    int n = 32;
#pragma unroll
    for (int d = 16; d >= 1; d >>= 1) {
        n >>= 1;
        bool hiSel = (lane & d) != 0;
#pragma unroll
        for (int i = 0; i < 16; i++) {
            if (i >= n) break;
            double send = hiSel ? s2[i] : s2[i + n];
            double recv = __shfl_xor_sync(0xffffffffu, send, d);
            double keep = hiSel ? s2[i + n] : s2[i];
            s2[i] = fadd2(keep, recv);
        }
    }
    float lo, hi; upk2(s2[0], lo, hi);
    float* addr = &g_y1[(o0 + (lane >> 3)) * 16 + 2 * (lane & 7)];
    asm volatile("red.global.add.v2.f32 [%0], {%1, %2};"
                 :: "l"(addr), "f"(lo), "f"(hi) : "memory");
}

// ---------------- dense2 + softmax ----------------
__global__ void dense2_kernel(const float* __restrict__ Wd2, float* __restrict__ out) {
    __shared__ float ys[O1];
    __shared__ float red[128];
    int b = blockIdx.x, t = threadIdx.x;
    for (int o = t; o < O1; o += 128) ys[o] = fmaxf(g_y1[o * 16 + b], 0.0f);
    __syncthreads();

    float logit = -1e30f;
    if (t < NCLS) {
        float s = 0.0f;
        const float* wr = Wd2 + t * O1;
        for (int o = 0; o < O1; o++) s = fmaf(ys[o], __ldg(wr + o), s);
        logit = s;
    }
    red[t] = logit;
    __syncthreads();
    for (int s = 64; s > 0; s >>= 1) {
        if (t < s) red[t] = fmaxf(red[t], red[t + s]);
        __syncthreads();
    }
    float mx = red[0];
    __syncthreads();
    float e = (t < NCLS) ? expf(logit - mx) : 0.0f;
    red[t] = e;
    __syncthreads();
    for (int s = 64; s > 0; s >>= 1) {
        if (t < s) red[t] += red[t + s];
        __syncthreads();
    }
    float sum = red[0];
    if (t < NCLS) out[b * NCLS + t] = e / sum;
}

// ---------------- launch ----------------
extern "C" void kernel_launch(void* const* d_in, const int* in_sizes, int n_in,
                              void* d_out, int out_size) {
    const float* x_src = (const float*)d_in[0];
    const float* x_dst = (const float*)d_in[1];
    const int*   ei    = (const int*)  d_in[2];
    const float* Wfd   = (const float*)d_in[3];
    const float* bfd   = (const float*)d_in[4];
    const float* Wl1   = (const float*)d_in[5];
    const float* bl1   = (const float*)d_in[6];
    const float* Wr1   = (const float*)d_in[7];
    const float* Wc1   = (const float*)d_in[11];
    const float* Wc2   = (const float*)d_in[12];
    const float* Wd1   = (const float*)d_in[13];
    const float* Wd2   = (const float*)d_in[14];
    float* out = (float*)d_out;

    float *p_xp, *p_o1, *p_o2;
    cudaGetSymbolAddress((void**)&p_xp, g_xp);
    cudaGetSymbolAddress((void**)&p_o1, g_out1);
    cudaGetSymbolAddress((void**)&p_o2, g_out2);

    cudaFuncSetAttribute(feat_kernel,   cudaFuncAttributeMaxDynamicSharedMemorySize, FEAT_SMEM);
    cudaFuncSetAttribute(conv_kernel,   cudaFuncAttributeMaxDynamicSharedMemorySize, CONV_SMEM);
    cudaFuncSetAttribute(dense1_kernel, cudaFuncAttributeMaxDynamicSharedMemorySize, D1_SMEM);

    feat_kernel<<<128, 256, FEAT_SMEM>>>(x_src, Wfd, bfd);                 // #1 (+zero)
    edge_kernel<<<4096, 256>>>(ei);                                        // #2
    node_kernel<<<6400, 256>>>(x_dst, Wl1, bl1, Wr1);                      // #3
    conv_kernel<<<dim3(16, 64), 200, CONV_SMEM>>>(p_xp, Wc1, p_o1, L0, L1V);   // #4
    conv_kernel<<<dim3(16, 64), 200, CONV_SMEM>>>(p_o1, Wc2, p_o2, L1V, L2V);  // #5
    dense1_kernel<<<dim3(400, 16), 256, D1_SMEM>>>(p_o2, Wd1);             // #6
    dense2_kernel<<<NB, 128>>>(Wd2, out);                                  // #7
}

// round 17
// speedup vs baseline: 1.2061x; 1.0016x over previous
#include <cuda_runtime.h>
#include <cstdint>

// ---------------- problem constants ----------------
#define NB       16
#define N_F      524288
#define N_P      65536
#define EH       2097152
#define E_TOTAL  4194304
#define XP_N     6553600
#define L0       4096
#define L1V      4095
#define L2V      4094
#define KDIM     409400
#define O1       500
#define NCLS     107

// ---------------- packed fp32x2 helpers ----------------
__device__ __forceinline__ double pk2(float lo, float hi) {
    double d; asm("mov.b64 %0, {%1, %2};" : "=d"(d) : "f"(lo), "f"(hi)); return d;
}
__device__ __forceinline__ void upk2(double d, float& lo, float& hi) {
    asm("mov.b64 {%0, %1}, %2;" : "=f"(lo), "=f"(hi) : "d"(d));
}
__device__ __forceinline__ double ffma2(double a, double b, double c) {
    double d; asm("fma.rn.f32x2 %0, %1, %2, %3;" : "=d"(d) : "d"(a), "d"(b), "d"(c)); return d;
}
__device__ __forceinline__ double fadd2(double a, double b) {
    double d; asm("add.rn.f32x2 %0, %1, %2;" : "=d"(d) : "d"(a), "d"(b)); return d;
}

// ---------------- scratch ----------------
__device__ float4 g_xf4[N_F];
__device__ float g_agg[N_P * 4];
__device__ float g_xp[XP_N];
__device__ float g_out1[NB * 100 * L1V];
__device__ float g_out2[NB * 100 * L2V];
__device__ float g_y1[O1 * NB];

// ---------------- feat (+ fused zero init) ----------------
#define FEAT_SMEM ((64 * 65 + 192 * 65) * 4)
__global__ __launch_bounds__(256)
void feat_kernel(const float* __restrict__ xsrc,
                 const float* __restrict__ Wfd,
                 const float* __restrict__ bfd) {
    int t0 = blockIdx.x * 256 + threadIdx.x;
#pragma unroll
    for (int z = t0; z < N_P * 4; z += 32768) g_agg[z] = 0.0f;
    if (t0 < O1 * NB) g_y1[t0] = 0.0f;

    extern __shared__ float sm[];
    float* xs = sm;             // [64][65]
    float* ws = sm + 64 * 65;   // [192][65]
    int t = threadIdx.x;
    int i0 = blockIdx.x << 6;

    for (int idx = t; idx < 4096; idx += 256) {
        int i = idx >> 6, k = idx & 63;
        xs[i * 65 + k] = xsrc[(i0 + i) * 64 + k];
    }
    for (int idx = t; idx < 12288; idx += 256) {
        int j = idx >> 6, k = idx & 63;
        ws[j * 65 + k] = Wfd[idx];
    }
    __syncthreads();

    int tx = t & 15, ty = t >> 4;
    float acc[4][12];
#pragma unroll
    for (int ii = 0; ii < 4; ii++)
#pragma unroll
        for (int jj = 0; jj < 12; jj++) acc[ii][jj] = 0.0f;

    for (int k = 0; k < 64; k++) {
        float xv[4], wv[12];
#pragma unroll
        for (int ii = 0; ii < 4; ii++) xv[ii] = xs[(ty * 4 + ii) * 65 + k];
#pragma unroll
        for (int jj = 0; jj < 12; jj++) wv[jj] = ws[(tx * 12 + jj) * 65 + k];
#pragma unroll
        for (int ii = 0; ii < 4; ii++)
#pragma unroll
            for (int jj = 0; jj < 12; jj++)
                acc[ii][jj] = fmaf(xv[ii], wv[jj], acc[ii][jj]);
    }

    int j0 = tx * 12;
#pragma unroll
    for (int ii = 0; ii < 4; ii++) {
        int i = i0 + ty * 4 + ii;
#pragma unroll
        for (int rr = 0; rr < 4; rr++) {
            int r = i * 64 + tx * 4 + rr;
            g_xf4[r] = make_float4(
                acc[ii][rr * 3 + 0] + __ldg(bfd + j0 + rr * 3 + 0),
                acc[ii][rr * 3 + 1] + __ldg(bfd + j0 + rr * 3 + 1),
                acc[ii][rr * 3 + 2] + __ldg(bfd + j0 + rr * 3 + 2),
                0.0f);
        }
    }
}

// ---------------- edge aggregation ----------------
__global__ void edge_kernel(const int* __restrict__ ei) {
    int e2 = blockIdx.x * 256 + threadIdx.x;
    int4 s4 = *reinterpret_cast<const int4*>(ei + 4 * e2);
    int4 d4 = *reinterpret_cast<const int4*>(ei + E_TOTAL + 4 * e2);
    float4 v0 = g_xf4[s4.x];
    float4 v1 = g_xf4[s4.z];
    float* a0 = g_agg + 4 * d4.x;
    float* a1 = g_agg + 4 * d4.z;
    asm volatile("red.global.add.v4.f32 [%0], {%1, %2, %3, %4};"
                 :: "l"(a0), "f"(v0.x), "f"(v0.y), "f"(v0.z), "f"(1.0f) : "memory");
    asm volatile("red.global.add.v4.f32 [%0], {%1, %2, %3, %4};"
                 :: "l"(a1), "f"(v1.x), "f"(v1.y), "f"(v1.z), "f"(1.0f) : "memory");
}

// ---------------- node update ----------------
__global__ __launch_bounds__(256)
void node_kernel(const float* __restrict__ xdst,
                 const float* __restrict__ Wl1,
                 const float* __restrict__ bl1,
                 const float* __restrict__ Wr1) {
    __shared__ float swl[300], swr[300], sb[100];
    int t = threadIdx.x;
    for (int idx = t; idx < 300; idx += 256) { swl[idx] = Wl1[idx]; swr[idx] = Wr1[idx]; }
    if (t < 100) sb[t] = bl1[t];
    __syncthreads();

    int gid = blockIdx.x * 256 + t;
    int n = gid / 25;
    int c0 = (gid - n * 25) * 4;
    float4 a = *reinterpret_cast<const float4*>(&g_agg[n * 4]);
    float inv = __fdividef(1.0f, fmaxf(a.w, 1.0f));
    float m0 = a.x * inv, m1 = a.y * inv, m2 = a.z * inv;
    const float* xd = xdst + 3 * n;
    float d0 = xd[0], d1 = xd[1], d2 = xd[2];
    float r[4];
#pragma unroll
    for (int cc = 0; cc < 4; cc++) {
        int c = c0 + cc;
        float v = sb[c];
        v = fmaf(m0, swl[c * 3 + 0], v);
        v = fmaf(m1, swl[c * 3 + 1], v);
        v = fmaf(m2, swl[c * 3 + 2], v);
        v = fmaf(d0, swr[c * 3 + 0], v);
        v = fmaf(d1, swr[c * 3 + 1], v);
        v = fmaf(d2, swr[c * 3 + 2], v);
        r[cc] = fmaxf(v, 0.0f);
    }
    *reinterpret_cast<float4*>(&g_xp[n * 100 + c0]) =
        make_float4(r[0], r[1], r[2], r[3]);
}

// ---------------- conv: full register double-buffer (x AND w prefetched) ---------
// 200 thr, h-tile 64, 2 blocks/SM (smem-bound). ~115 regs, no cap -> no spills.
#define CONV_SMEM ((100 * 202 + 100 * 68) * 4)
__global__ __launch_bounds__(200)
void conv_kernel(const float* __restrict__ in, const float* __restrict__ W,
                 float* __restrict__ out, int Lin, int Lout) {
    extern __shared__ float sm[];
    float* ws = sm;               // [o][202]
    float* xs = sm + 100 * 202;   // [i][68]
    int b  = blockIdx.x;
    int h0 = blockIdx.y << 6;
    int t  = threadIdx.x;

    for (int idx = t; idx < 20000; idx += 200) {
        int o = idx / 200;
        ws[o * 202 + (idx - o * 200)] = W[idx];
    }
    int nj = Lin - h0; if (nj > 65) nj = 65;
    const float* inb = in + b * 100 * Lin + h0;
    for (int idx = t; idx < 6800; idx += 200) {
        int i = idx / 68;
        int j = idx - i * 68;
        xs[idx] = (j < nj) ? inb[i * Lin + j] : 0.0f;
    }
    __syncthreads();

    int og = t >> 3, ht = t & 7;
    int o0 = og << 2, hh = ht << 3;
    double acc2[4][8];
#pragma unroll
    for (int oo = 0; oo < 4; oo++)
#pragma unroll
        for (int j = 0; j < 8; j++) acc2[oo][j] = 0.0;

    // prologue: x row + 4 w-pairs for i=0
    float4 xA, xB; float x8;
    double wd[4];
    {
        const float* xr = xs + hh;
        xA = *reinterpret_cast<const float4*>(xr);
        xB = *reinterpret_cast<const float4*>(xr + 4);
        x8 = xr[8];
#pragma unroll
        for (int oo = 0; oo < 4; oo++)
            wd[oo] = *reinterpret_cast<const double*>(&ws[(o0 + oo) * 202]);
    }

    for (int i = 0; i < 100; i++) {
        // pairs from prefetched registers (no LDS dependency this iteration)
        double xp[8];
        xp[0] = pk2(xA.x, xA.y); xp[1] = pk2(xA.y, xA.z);
        xp[2] = pk2(xA.z, xA.w); xp[3] = pk2(xA.w, xB.x);
        xp[4] = pk2(xB.x, xB.y); xp[5] = pk2(xB.y, xB.z);
        xp[6] = pk2(xB.z, xB.w); xp[7] = pk2(xB.w, x8);

        // issue next-iteration w loads early
        double wn[4];
        if (i < 99) {
#pragma unroll
            for (int oo = 0; oo < 4; oo++)
                wn[oo] = *reinterpret_cast<const double*>(&ws[(o0 + oo) * 202 + (i + 1) * 2]);
        }

        // FMAs oo = 0,1 with current (prefetched) w
#pragma unroll
        for (int oo = 0; oo < 2; oo++)
#pragma unroll
            for (int j = 0; j < 8; j++)
                acc2[oo][j] = ffma2(wd[oo], xp[j], acc2[oo][j]);

        // issue next-iteration x loads
        if (i < 99) {
            const float* xrn = xs + (i + 1) * 68 + hh;
            xA = *reinterpret_cast<const float4*>(xrn);
            xB = *reinterpret_cast<const float4*>(xrn + 4);
            x8 = xrn[8];
        }

        // FMAs oo = 2,3
#pragma unroll
        for (int oo = 2; oo < 4; oo++)
#pragma unroll
            for (int j = 0; j < 8; j++)
                acc2[oo][j] = ffma2(wd[oo], xp[j], acc2[oo][j]);

        if (i < 99) {
#pragma unroll
            for (int oo = 0; oo < 4; oo++) wd[oo] = wn[oo];
        }
    }

    float* outb = out + b * 100 * Lout;
#pragma unroll
    for (int oo = 0; oo < 4; oo++)
#pragma unroll
        for (int j = 0; j < 8; j++) {
            int h = h0 + hh + j;
            if (h < Lout) {
                float lo, hi; upk2(acc2[oo][j], lo, hi);
                outb[(o0 + oo) * Lout + h] = fmaxf(lo + hi, 0.0f);
            }
        }
}

// ---------------- dense1 v4 (champion, verbatim) ----------------
#define D1_SMEM (1024 * 20 * 4)
__global__ __launch_bounds__(256, 2)
void dense1_kernel(const float* __restrict__ x2, const float* __restrict__ W) {
    extern __shared__ float xs[];   // [1024][20]
    int t = threadIdx.x;
    int k0 = blockIdx.x << 10;
    int KN = KDIM - k0; if (KN > 1024) KN = 1024;

    for (int idx = t; idx < 4096; idx += 256) {
        int b  = idx & 15;
        int kk = (idx >> 4) << 2;
        float4 v = make_float4(0.f, 0.f, 0.f, 0.f);
        if (kk < KN)
            v = *reinterpret_cast<const float4*>(x2 + (size_t)b * KDIM + k0 + kk);
        xs[(kk + 0) * 20 + b] = v.x;
        xs[(kk + 1) * 20 + b] = v.y;
        xs[(kk + 2) * 20 + b] = v.z;
        xs[(kk + 3) * 20 + b] = v.w;
    }
    __syncthreads();

    int wid = t >> 5, lane = t & 31;
    int o0 = (blockIdx.y << 5) + (wid << 2);
    if (o0 >= O1) return;

    double acc2[4][8];
#pragma unroll
    for (int o = 0; o < 4; o++)
#pragma unroll
        for (int bp = 0; bp < 8; bp++) acc2[o][bp] = 0.0;

    const float* wbase = W + (size_t)o0 * KDIM + k0;

    float wbuf[4][4];
#pragma unroll
    for (int p = 0; p < 4; p++) {
        int k = lane + (p << 5);
#pragma unroll
        for (int o = 0; o < 4; o++)
            wbuf[p][o] = (k < KN) ? __ldg(wbase + (size_t)o * KDIM + k) : 0.0f;
    }

#pragma unroll 4
    for (int it = 0; it < 32; it++) {
        int slot = it & 3;
        int k = lane + (it << 5);

        double wd[4];
#pragma unroll
        for (int o = 0; o < 4; o++) wd[o] = pk2(wbuf[slot][o], wbuf[slot][o]);

        int kn = k + 128;
#pragma unroll
        for (int o = 0; o < 4; o++)
            wbuf[slot][o] = (kn < KN) ? __ldg(wbase + (size_t)o * KDIM + kn) : 0.0f;

        const double2* xrow = reinterpret_cast<const double2*>(&xs[k * 20]);
        double2 x01 = xrow[0], x23 = xrow[1], x45 = xrow[2], x67 = xrow[3];
        double xp[8] = {x01.x, x01.y, x23.x, x23.y, x45.x, x45.y, x67.x, x67.y};

#pragma unroll
        for (int o = 0; o < 4; o++)
#pragma unroll
            for (int bp = 0; bp < 8; bp++)
                acc2[o][bp] = ffma2(wd[o], xp[bp], acc2[o][bp]);
    }

    double s2[32];
#pragma unroll
    for (int a = 0; a < 32; a++) s2[a] = acc2[a >> 3][a & 7];
    int n = 32;
#pragma unroll
    for (int d = 16; d >= 1; d >>= 1) {
        n >>= 1;
        bool hiSel = (lane & d) != 0;
#pragma unroll
        for (int i = 0; i < 16; i++) {
            if (i >= n) break;
            double send = hiSel ? s2[i] : s2[i + n];
            double recv = __shfl_xor_sync(0xffffffffu, send, d);
            double keep = hiSel ? s2[i + n] : s2[i];
            s2[i] = fadd2(keep, recv);
        }
    }
    float lo, hi; upk2(s2[0], lo, hi);
    float* addr = &g_y1[(o0 + (lane >> 3)) * 16 + 2 * (lane & 7)];
    asm volatile("red.global.add.v2.f32 [%0], {%1, %2};"
                 :: "l"(addr), "f"(lo), "f"(hi) : "memory");
}

// ---------------- dense2 + softmax ----------------
__global__ void dense2_kernel(const float* __restrict__ Wd2, float* __restrict__ out) {
    __shared__ float ys[O1];
    __shared__ float red[128];
    int b = blockIdx.x, t = threadIdx.x;
    for (int o = t; o < O1; o += 128) ys[o] = fmaxf(g_y1[o * 16 + b], 0.0f);
    __syncthreads();

    float logit = -1e30f;
    if (t < NCLS) {
        float s = 0.0f;
        const float* wr = Wd2 + t * O1;
        for (int o = 0; o < O1; o++) s = fmaf(ys[o], __ldg(wr + o), s);
        logit = s;
    }
    red[t] = logit;
    __syncthreads();
    for (int s = 64; s > 0; s >>= 1) {
        if (t < s) red[t] = fmaxf(red[t], red[t + s]);
        __syncthreads();
    }
    float mx = red[0];
    __syncthreads();
    float e = (t < NCLS) ? expf(logit - mx) : 0.0f;
    red[t] = e;
    __syncthreads();
    for (int s = 64; s > 0; s >>= 1) {
        if (t < s) red[t] += red[t + s];
        __syncthreads();
    }
    float sum = red[0];
    if (t < NCLS) out[b * NCLS + t] = e / sum;
}

// ---------------- launch ----------------
extern "C" void kernel_launch(void* const* d_in, const int* in_sizes, int n_in,
                              void* d_out, int out_size) {
    const float* x_src = (const float*)d_in[0];
    const float* x_dst = (const float*)d_in[1];
    const int*   ei    = (const int*)  d_in[2];
    const float* Wfd   = (const float*)d_in[3];
    const float* bfd   = (const float*)d_in[4];
    const float* Wl1   = (const float*)d_in[5];
    const float* bl1   = (const float*)d_in[6];
    const float* Wr1   = (const float*)d_in[7];
    const float* Wc1   = (const float*)d_in[11];
    const float* Wc2   = (const float*)d_in[12];
    const float* Wd1   = (const float*)d_in[13];
    const float* Wd2   = (const float*)d_in[14];
    float* out = (float*)d_out;

    float *p_xp, *p_o1, *p_o2;
    cudaGetSymbolAddress((void**)&p_xp, g_xp);
    cudaGetSymbolAddress((void**)&p_o1, g_out1);
    cudaGetSymbolAddress((void**)&p_o2, g_out2);

    cudaFuncSetAttribute(feat_kernel,   cudaFuncAttributeMaxDynamicSharedMemorySize, FEAT_SMEM);
    cudaFuncSetAttribute(conv_kernel,   cudaFuncAttributeMaxDynamicSharedMemorySize, CONV_SMEM);
    cudaFuncSetAttribute(dense1_kernel, cudaFuncAttributeMaxDynamicSharedMemorySize, D1_SMEM);

    feat_kernel<<<128, 256, FEAT_SMEM>>>(x_src, Wfd, bfd);                 // #1 (+zero)
    edge_kernel<<<4096, 256>>>(ei);                                        // #2
    node_kernel<<<6400, 256>>>(x_dst, Wl1, bl1, Wr1);                      // #3
    conv_kernel<<<dim3(16, 64), 200, CONV_SMEM>>>(p_xp, Wc1, p_o1, L0, L1V);   // #4
    conv_kernel<<<dim3(16, 64), 200, CONV_SMEM>>>(p_o1, Wc2, p_o2, L1V, L2V);  // #5
    dense1_kernel<<<dim3(400, 16), 256, D1_SMEM>>>(p_o2, Wd1);             // #6
    dense2_kernel<<<NB, 128>>>(Wd2, out);                                  // #7
}